// round 12
// baseline (speedup 1.0000x reference)
#include <cuda_runtime.h>
#include <cuda_fp16.h>
#include <cuda_bf16.h>
#include <cstdint>

#define NUM_NODES 100000
#define EMBED_DIM 64
#define NUM_EDGES 3200000
#define NUM_LAYERS 3

#define SCAN_BS 1024
#define SCAN_NB ((NUM_NODES + SCAN_BS - 1) / SCAN_BS)   // 98

// ---------------- scratch (device globals; no runtime allocation) ----------------
__device__ int    g_is64;                // 1 if edge_index really is int64
__device__ int    g_deg[NUM_NODES];
__device__ float  g_dinv[NUM_NODES];
__device__ int    g_rowptr[NUM_NODES + 1];
__device__ int    g_cursor[NUM_NODES];
__device__ int    g_bsum[SCAN_NB];
__device__ int    g_csr_src[NUM_EDGES];
// fp16 ping-pong propagation state: y = dinv * x, stored as half2 pairs
__device__ __half2 g_y0[(size_t)NUM_NODES * (EMBED_DIM / 2)];
__device__ __half2 g_y1[(size_t)NUM_NODES * (EMBED_DIM / 2)];

// ---------------- helpers ----------------

__device__ __forceinline__ int clamp_idx(long long v) {
    return ((unsigned long long)v >= (unsigned long long)NUM_NODES) ? -1 : (int)v;
}

// ---------------- kernels ----------------

// Fused: dtype detect (thread 0) + zero the degree array (all threads).
__global__ void k_init(const void* ei) {
    int i = blockIdx.x * blockDim.x + threadIdx.x;
    if (i == 0) {
        const unsigned long long* p = (const unsigned long long*)ei;
        int all_hi_zero = 1;
        for (int k = 0; k < 256; k++) {
            if ((p[k] >> 32) != 0ull) { all_hi_zero = 0; break; }
        }
        g_is64 = all_hi_zero;
    }
    if (i < NUM_NODES) g_deg[i] = 0;
}

// Histogram of dst, 4 edges per thread (vectorized loads).
__global__ void k_hist(const void* __restrict__ ei) {
    int t = blockIdx.x * blockDim.x + threadIdx.x;
    int e0 = t * 4;
    if (e0 >= NUM_EDGES) return;
    int d0, d1, d2, d3;
    if (g_is64) {
        const longlong2* p = (const longlong2*)((const long long*)ei + NUM_EDGES);
        longlong2 a = p[t * 2];
        longlong2 b = p[t * 2 + 1];
        d0 = clamp_idx(a.x); d1 = clamp_idx(a.y);
        d2 = clamp_idx(b.x); d3 = clamp_idx(b.y);
    } else {
        const int4* p = (const int4*)((const int*)ei + NUM_EDGES);
        int4 a = p[t];
        d0 = clamp_idx(a.x); d1 = clamp_idx(a.y);
        d2 = clamp_idx(a.z); d3 = clamp_idx(a.w);
    }
    if (d0 >= 0) atomicAdd(&g_deg[d0], 1);
    if (d1 >= 0) atomicAdd(&g_deg[d1], 1);
    if (d2 >= 0) atomicAdd(&g_deg[d2], 1);
    if (d3 >= 0) atomicAdd(&g_deg[d3], 1);
}

// scan phase 1: per-block sums of deg; fused dinv computation (same index space)
__global__ void k_block_sums() {
    __shared__ int sh[SCAN_BS];
    int tid = threadIdx.x;
    int i = blockIdx.x * SCAN_BS + tid;
    int d = (i < NUM_NODES) ? g_deg[i] : 0;
    if (i < NUM_NODES) g_dinv[i] = (d > 0) ? rsqrtf((float)d) : 0.0f;
    sh[tid] = d;
    __syncthreads();
    for (int off = SCAN_BS / 2; off > 0; off >>= 1) {
        if (tid < off) sh[tid] += sh[tid + off];
        __syncthreads();
    }
    if (tid == 0) g_bsum[blockIdx.x] = sh[0];
}

// scan phase 2+3 fused: each block computes its own base offset by a parallel
// reduction over g_bsum[0..blockIdx), then does its local exclusive scan.
__global__ void k_scan_blocks() {
    __shared__ int sh[SCAN_BS];
    __shared__ int s_boff;
    int tid = threadIdx.x;

    // parallel reduce bsum[0..blockIdx.x) (blockIdx.x <= 97 < SCAN_BS)
    sh[tid] = (tid < blockIdx.x) ? g_bsum[tid] : 0;
    __syncthreads();
    for (int off = SCAN_BS / 2; off > 0; off >>= 1) {
        if (tid < off) sh[tid] += sh[tid + off];
        __syncthreads();
    }
    if (tid == 0) s_boff = sh[0];
    __syncthreads();
    int boff = s_boff;
    __syncthreads();                      // sh about to be reused

    int i = blockIdx.x * SCAN_BS + tid;
    int v = (i < NUM_NODES) ? g_deg[i] : 0;
    sh[tid] = v;
    __syncthreads();
    // Hillis-Steele inclusive scan
    for (int off = 1; off < SCAN_BS; off <<= 1) {
        int t = (tid >= off) ? sh[tid - off] : 0;
        __syncthreads();
        sh[tid] += t;
        __syncthreads();
    }
    if (i < NUM_NODES) {
        int excl = sh[tid] - v + boff;
        g_rowptr[i] = excl;
        g_cursor[i] = excl;
        if (i == NUM_NODES - 1) g_rowptr[NUM_NODES] = excl + v;
    }
}

// Fused: CSR scatter (src only, 2 edges/thread) + layer-0 prescale
// (y0 = dinv*emb as fp16, 2 half2/thread from one float4).
__global__ void k_scatter_prescale(const void* __restrict__ ei,
                                   const float* __restrict__ emb) {
    int t = blockIdx.x * blockDim.x + threadIdx.x;
    int e0 = t * 2;
    if (e0 < NUM_EDGES) {
        int s0, s1, d0, d1;
        if (g_is64) {
            const longlong2* ps = (const longlong2*)((const long long*)ei);
            const longlong2* pd = (const longlong2*)((const long long*)ei + NUM_EDGES);
            longlong2 sv = ps[t], dv = pd[t];
            s0 = clamp_idx(sv.x); s1 = clamp_idx(sv.y);
            d0 = clamp_idx(dv.x); d1 = clamp_idx(dv.y);
        } else {
            const int2* ps = (const int2*)((const int*)ei);
            const int2* pd = (const int2*)((const int*)ei + NUM_EDGES);
            int2 sv = ps[t], dv = pd[t];
            s0 = clamp_idx(sv.x); s1 = clamp_idx(sv.y);
            d0 = clamp_idx(dv.x); d1 = clamp_idx(dv.y);
        }
        if (s0 >= 0 && d0 >= 0) {
            int pos = atomicAdd(&g_cursor[d0], 1);
            if ((unsigned)pos < (unsigned)NUM_EDGES) g_csr_src[pos] = s0;
        }
        if (s1 >= 0 && d1 >= 0) {
            int pos = atomicAdd(&g_cursor[d1], 1);
            if ((unsigned)pos < (unsigned)NUM_EDGES) g_csr_src[pos] = s1;
        }
    }
    // prescale: 3.2M half2 elements, 2 per thread. p0 = 2t is even, so
    // p0 and p0+1 always lie in the same 32-element node row.
    int p0 = t * 2;
    if (p0 < NUM_NODES * (EMBED_DIM / 2)) {
        int node = p0 >> 5;
        float sc = g_dinv[node];
        float4 v = ((const float4*)emb)[t];
        g_y0[p0]     = __floats2half2_rn(sc * v.x, sc * v.y);
        g_y0[p0 + 1] = __floats2half2_rn(sc * v.z, sc * v.w);
    }
}

// SpMM with separable normalization:
//   acc[d]    = Σ_{e: dst=d} y[src(e)]
//   x_next[d] = dinv[d] * acc                 -> out += x_next / 4
//   y_next[d] = dinv[d]^2 * acc               (pre-scaled for next layer)
// One warp per dst row; lane owns a half2. Full 32-edge batches fully unrolled.
__global__ void k_spmm(const float* __restrict__ emb,
                       float* __restrict__ out,
                       int layer) {
    int warps_per_block = blockDim.x >> 5;
    int row = blockIdx.x * warps_per_block + (threadIdx.x >> 5);
    if (row >= NUM_NODES) return;
    int lane = threadIdx.x & 31;

    const __half2* y_in  = (layer == 1) ? g_y1 : g_y0;
    __half2*       y_out = (layer == 0) ? g_y1 : g_y0;

    int beg = g_rowptr[row];
    int end = g_rowptr[row + 1];

    float2 acc = make_float2(0.0f, 0.0f);
    for (int b = beg; b < end; b += 32) {
        int n = end - b;
        if (n >= 32) {
            int s = g_csr_src[b + lane];
            #pragma unroll
            for (int j = 0; j < 32; ++j) {
                int sj = __shfl_sync(0xffffffffu, s, j);
                float2 v = __half22float2(y_in[(size_t)sj * (EMBED_DIM / 2) + lane]);
                acc.x += v.x;
                acc.y += v.y;
            }
        } else {
            int s = (lane < n) ? g_csr_src[b + lane] : 0;
            #pragma unroll 8
            for (int j = 0; j < n; ++j) {
                int sj = __shfl_sync(0xffffffffu, s, j);
                float2 v = __half22float2(y_in[(size_t)sj * (EMBED_DIM / 2) + lane]);
                acc.x += v.x;
                acc.y += v.y;
            }
        }
    }

    float di = g_dinv[row];
    float xn_x = di * acc.x;
    float xn_y = di * acc.y;

    if (layer != 2) {                // last layer's y is never read
        y_out[(size_t)row * (EMBED_DIM / 2) + lane] =
            __floats2half2_rn(di * xn_x, di * xn_y);
    }

    float2* op = (float2*)(out + (size_t)row * EMBED_DIM);
    const float inv = 1.0f / (NUM_LAYERS + 1);
    if (layer == 0) {
        const float2* ep = (const float2*)(emb + (size_t)row * EMBED_DIM);
        float2 ev = ep[lane];
        op[lane] = make_float2(inv * (ev.x + xn_x), inv * (ev.y + xn_y));
    } else {
        float2 prev = op[lane];
        op[lane] = make_float2(prev.x + inv * xn_x, prev.y + inv * xn_y);
    }
}

// ---------------- launch ----------------

extern "C" void kernel_launch(void* const* d_in, const int* in_sizes, int n_in,
                              void* d_out, int out_size) {
    const float* emb = (const float*)d_in[0];
    const void*  ei  = d_in[1];          // int32 or int64 — detected on device
    float*       out = (float*)d_out;

    const int TB = 256;
    const int node_blocks  = (NUM_NODES + TB - 1) / TB;
    const int hist_threads = NUM_EDGES / 4;
    const int scat_threads = NUM_EDGES / 2;

    k_init<<<node_blocks, TB>>>(ei);
    k_hist<<<(hist_threads + TB - 1) / TB, TB>>>(ei);

    k_block_sums<<<SCAN_NB, SCAN_BS>>>();
    k_scan_blocks<<<SCAN_NB, SCAN_BS>>>();

    k_scatter_prescale<<<(scat_threads + TB - 1) / TB, TB>>>(ei, emb);

    const int WPB = TB / 32;                                   // 8 warps/block
    const int spmm_blocks = (NUM_NODES + WPB - 1) / WPB;       // 12500

    k_spmm<<<spmm_blocks, TB>>>(emb, out, 0);
    k_spmm<<<spmm_blocks, TB>>>(emb, out, 1);
    k_spmm<<<spmm_blocks, TB>>>(emb, out, 2);
}

// round 14
// speedup vs baseline: 1.4626x; 1.4626x over previous
#include <cuda_runtime.h>
#include <cuda_fp16.h>
#include <cuda_bf16.h>
#include <cstdint>

#define NUM_NODES 100000
#define EMBED_DIM 64
#define NUM_EDGES 3200000
#define NUM_LAYERS 3

#define SCAN_BS 1024
#define SCAN_NB ((NUM_NODES + SCAN_BS - 1) / SCAN_BS)   // 98

// ---------------- scratch (device globals; no runtime allocation) ----------------
__device__ int    g_is64;                // 1 if edge_index really is int64
__device__ int    g_deg[NUM_NODES];
__device__ float  g_dinv[NUM_NODES];
__device__ int    g_rowptr[NUM_NODES + 1];
__device__ int    g_cursor[NUM_NODES];
__device__ int    g_bsum[SCAN_NB];
__device__ int    g_csr_src[NUM_EDGES];
// fp16 ping-pong propagation state: y = dinv * x, stored as half2 pairs
__device__ __half2 g_y0[(size_t)NUM_NODES * (EMBED_DIM / 2)];
__device__ __half2 g_y1[(size_t)NUM_NODES * (EMBED_DIM / 2)];

// ---------------- helpers ----------------

// Fetch edge endpoint `e` of row `row` (0=src, 1=dst), honoring detected dtype.
// Returns -1 if out of range (defensive: surface as rel_err, never crash).
__device__ __forceinline__ int load_idx(const void* ei, int row, int e) {
    long long v;
    if (g_is64) {
        v = ((const long long*)ei)[(size_t)row * NUM_EDGES + e];
    } else {
        v = ((const int*)ei)[(size_t)row * NUM_EDGES + e];
    }
    if ((unsigned long long)v >= (unsigned long long)NUM_NODES) return -1;
    return (int)v;
}

// ---------------- kernels ----------------

// Fused: dtype detect (thread 0) + zero the degree array (all threads).
__global__ void k_init(const void* ei) {
    int i = blockIdx.x * blockDim.x + threadIdx.x;
    if (i == 0) {
        const unsigned long long* p = (const unsigned long long*)ei;
        int all_hi_zero = 1;
        for (int k = 0; k < 256; k++) {
            if ((p[k] >> 32) != 0ull) { all_hi_zero = 0; break; }
        }
        g_is64 = all_hi_zero;
    }
    if (i < NUM_NODES) g_deg[i] = 0;
}

// Histogram of dst — scalar, 1 edge per thread (R11-proven form).
__global__ void k_hist(const void* __restrict__ ei) {
    int e = blockIdx.x * blockDim.x + threadIdx.x;
    if (e < NUM_EDGES) {
        int d = load_idx(ei, 1, e);
        if (d >= 0) atomicAdd(&g_deg[d], 1);
    }
}

// scan phase 1: per-block sums of deg; fused dinv computation (same index space)
__global__ void k_block_sums() {
    __shared__ int sh[SCAN_BS];
    int tid = threadIdx.x;
    int i = blockIdx.x * SCAN_BS + tid;
    int d = (i < NUM_NODES) ? g_deg[i] : 0;
    if (i < NUM_NODES) g_dinv[i] = (d > 0) ? rsqrtf((float)d) : 0.0f;
    sh[tid] = d;
    __syncthreads();
    for (int off = SCAN_BS / 2; off > 0; off >>= 1) {
        if (tid < off) sh[tid] += sh[tid + off];
        __syncthreads();
    }
    if (tid == 0) g_bsum[blockIdx.x] = sh[0];
}

// scan phase 2+3 fused (ncu-verified: 8.7us, replaces the 8.3us serial kernel):
// each block computes its base offset via parallel reduction over
// g_bsum[0..blockIdx), then does its local exclusive scan.
__global__ void k_scan_blocks() {
    __shared__ int sh[SCAN_BS];
    __shared__ int s_boff;
    int tid = threadIdx.x;

    // parallel reduce bsum[0..blockIdx.x) (blockIdx.x <= 97 < SCAN_BS)
    sh[tid] = (tid < blockIdx.x) ? g_bsum[tid] : 0;
    __syncthreads();
    for (int off = SCAN_BS / 2; off > 0; off >>= 1) {
        if (tid < off) sh[tid] += sh[tid + off];
        __syncthreads();
    }
    if (tid == 0) s_boff = sh[0];
    __syncthreads();
    int boff = s_boff;
    __syncthreads();                      // sh about to be reused

    int i = blockIdx.x * SCAN_BS + tid;
    int v = (i < NUM_NODES) ? g_deg[i] : 0;
    sh[tid] = v;
    __syncthreads();
    // Hillis-Steele inclusive scan
    for (int off = 1; off < SCAN_BS; off <<= 1) {
        int t = (tid >= off) ? sh[tid - off] : 0;
        __syncthreads();
        sh[tid] += t;
        __syncthreads();
    }
    if (i < NUM_NODES) {
        int excl = sh[tid] - v + boff;
        g_rowptr[i] = excl;
        g_cursor[i] = excl;
        if (i == NUM_NODES - 1) g_rowptr[NUM_NODES] = excl + v;
    }
}

// Fused: CSR scatter (src only) + layer-0 prescale (y0 = dinv*emb as fp16).
// Scalar, 1 edge / 1 half2 per thread (R11-proven form).
__global__ void k_scatter_prescale(const void* __restrict__ ei,
                                   const float* __restrict__ emb) {
    int e = blockIdx.x * blockDim.x + threadIdx.x;
    if (e < NUM_EDGES) {
        int s = load_idx(ei, 0, e);
        int d = load_idx(ei, 1, e);
        if (s >= 0 && d >= 0) {
            int pos = atomicAdd(&g_cursor[d], 1);
            if ((unsigned)pos < (unsigned)NUM_EDGES) g_csr_src[pos] = s;
        }
    }
    // prescale: NUM_NODES * 32 = 3.2M half2 elements — same index space
    if (e < NUM_NODES * (EMBED_DIM / 2)) {
        int node = e >> 5;
        float sc = g_dinv[node];
        float2 v = ((const float2*)emb)[e];
        g_y0[e] = __floats2half2_rn(sc * v.x, sc * v.y);
    }
}

// SpMM with separable normalization:
//   acc[d]    = Σ_{e: dst=d} y[src(e)]
//   x_next[d] = dinv[d] * acc                 -> out += x_next / 4
//   y_next[d] = dinv[d]^2 * acc               (pre-scaled for next layer)
// One warp per dst row; lane owns a half2. Full 32-edge batches fully unrolled.
__global__ void k_spmm(const float* __restrict__ emb,
                       float* __restrict__ out,
                       int layer) {
    int warps_per_block = blockDim.x >> 5;
    int row = blockIdx.x * warps_per_block + (threadIdx.x >> 5);
    if (row >= NUM_NODES) return;
    int lane = threadIdx.x & 31;

    const __half2* y_in  = (layer == 1) ? g_y1 : g_y0;
    __half2*       y_out = (layer == 0) ? g_y1 : g_y0;

    int beg = g_rowptr[row];
    int end = g_rowptr[row + 1];

    float2 acc = make_float2(0.0f, 0.0f);
    for (int b = beg; b < end; b += 32) {
        int n = end - b;
        if (n >= 32) {
            int s = g_csr_src[b + lane];
            #pragma unroll
            for (int j = 0; j < 32; ++j) {
                int sj = __shfl_sync(0xffffffffu, s, j);
                float2 v = __half22float2(y_in[(size_t)sj * (EMBED_DIM / 2) + lane]);
                acc.x += v.x;
                acc.y += v.y;
            }
        } else {
            int s = (lane < n) ? g_csr_src[b + lane] : 0;
            #pragma unroll 8
            for (int j = 0; j < n; ++j) {
                int sj = __shfl_sync(0xffffffffu, s, j);
                float2 v = __half22float2(y_in[(size_t)sj * (EMBED_DIM / 2) + lane]);
                acc.x += v.x;
                acc.y += v.y;
            }
        }
    }

    float di = g_dinv[row];
    float xn_x = di * acc.x;
    float xn_y = di * acc.y;

    if (layer != 2) {                // last layer's y is never read
        y_out[(size_t)row * (EMBED_DIM / 2) + lane] =
            __floats2half2_rn(di * xn_x, di * xn_y);
    }

    float2* op = (float2*)(out + (size_t)row * EMBED_DIM);
    const float inv = 1.0f / (NUM_LAYERS + 1);
    if (layer == 0) {
        const float2* ep = (const float2*)(emb + (size_t)row * EMBED_DIM);
        float2 ev = ep[lane];
        op[lane] = make_float2(inv * (ev.x + xn_x), inv * (ev.y + xn_y));
    } else {
        float2 prev = op[lane];
        op[lane] = make_float2(prev.x + inv * xn_x, prev.y + inv * xn_y);
    }
}

// ---------------- launch ----------------

extern "C" void kernel_launch(void* const* d_in, const int* in_sizes, int n_in,
                              void* d_out, int out_size) {
    const float* emb = (const float*)d_in[0];
    const void*  ei  = d_in[1];          // int32 or int64 — detected on device
    float*       out = (float*)d_out;

    const int TB = 256;
    const int node_blocks = (NUM_NODES + TB - 1) / TB;
    const int edge_blocks = (NUM_EDGES + TB - 1) / TB;

    k_init<<<node_blocks, TB>>>(ei);
    k_hist<<<edge_blocks, TB>>>(ei);

    k_block_sums<<<SCAN_NB, SCAN_BS>>>();
    k_scan_blocks<<<SCAN_NB, SCAN_BS>>>();

    k_scatter_prescale<<<edge_blocks, TB>>>(ei, emb);

    const int WPB = TB / 32;                                   // 8 warps/block
    const int spmm_blocks = (NUM_NODES + WPB - 1) / WPB;       // 12500

    k_spmm<<<spmm_blocks, TB>>>(emb, out, 0);
    k_spmm<<<spmm_blocks, TB>>>(emb, out, 1);
    k_spmm<<<spmm_blocks, TB>>>(emb, out, 2);
}

// round 16
// speedup vs baseline: 1.5676x; 1.0718x over previous
#include <cuda_runtime.h>
#include <cuda_fp16.h>
#include <cuda_bf16.h>
#include <cstdint>

#define NUM_NODES 100000
#define EMBED_DIM 64
#define NUM_EDGES 3200000
#define NUM_LAYERS 3

#define SCAN_BS 1024
#define SCAN_NB ((NUM_NODES + SCAN_BS - 1) / SCAN_BS)   // 98

// ---------------- scratch (device globals; no runtime allocation) ----------------
__device__ int    g_is64;                // 1 if edge_index really is int64
__device__ int    g_deg[NUM_NODES];
__device__ float  g_dinv[NUM_NODES];
__device__ int    g_rowptr[NUM_NODES + 1];
__device__ int    g_cursor[NUM_NODES];
__device__ int    g_bsum[SCAN_NB];
__device__ int    g_csr_src[NUM_EDGES];
// fp16 ping-pong propagation state: y = dinv * x, stored as half2 pairs
__device__ __half2 g_y0[(size_t)NUM_NODES * (EMBED_DIM / 2)];
__device__ __half2 g_y1[(size_t)NUM_NODES * (EMBED_DIM / 2)];

// ---------------- helpers ----------------

// Fetch edge endpoint `e` of row `row` (0=src, 1=dst), honoring detected dtype.
// Returns -1 if out of range (defensive: surface as rel_err, never crash).
__device__ __forceinline__ int load_idx(const void* ei, int row, int e) {
    long long v;
    if (g_is64) {
        v = ((const long long*)ei)[(size_t)row * NUM_EDGES + e];
    } else {
        v = ((const int*)ei)[(size_t)row * NUM_EDGES + e];
    }
    if ((unsigned long long)v >= (unsigned long long)NUM_NODES) return -1;
    return (int)v;
}

// ---------------- kernels ----------------

// Fused: dtype detect (thread 0) + zero the degree array (all threads).
__global__ void k_init(const void* ei) {
    int i = blockIdx.x * blockDim.x + threadIdx.x;
    if (i == 0) {
        const unsigned long long* p = (const unsigned long long*)ei;
        int all_hi_zero = 1;
        for (int k = 0; k < 256; k++) {
            if ((p[k] >> 32) != 0ull) { all_hi_zero = 0; break; }
        }
        g_is64 = all_hi_zero;
    }
    if (i < NUM_NODES) g_deg[i] = 0;
}

// Histogram of dst — scalar, 1 edge per thread (R11-proven form).
__global__ void k_hist(const void* __restrict__ ei) {
    int e = blockIdx.x * blockDim.x + threadIdx.x;
    if (e < NUM_EDGES) {
        int d = load_idx(ei, 1, e);
        if (d >= 0) atomicAdd(&g_deg[d], 1);
    }
}

// scan phase 1: per-block sums of deg; fused dinv computation (same index space)
__global__ void k_block_sums() {
    __shared__ int sh[SCAN_BS];
    int tid = threadIdx.x;
    int i = blockIdx.x * SCAN_BS + tid;
    int d = (i < NUM_NODES) ? g_deg[i] : 0;
    if (i < NUM_NODES) g_dinv[i] = (d > 0) ? rsqrtf((float)d) : 0.0f;
    sh[tid] = d;
    __syncthreads();
    for (int off = SCAN_BS / 2; off > 0; off >>= 1) {
        if (tid < off) sh[tid] += sh[tid + off];
        __syncthreads();
    }
    if (tid == 0) g_bsum[blockIdx.x] = sh[0];
}

// scan phase 2+3 fused (ncu-verified): each block computes its base offset via
// parallel reduction over g_bsum[0..blockIdx), then does its local scan.
__global__ void k_scan_blocks() {
    __shared__ int sh[SCAN_BS];
    __shared__ int s_boff;
    int tid = threadIdx.x;

    sh[tid] = (tid < blockIdx.x) ? g_bsum[tid] : 0;
    __syncthreads();
    for (int off = SCAN_BS / 2; off > 0; off >>= 1) {
        if (tid < off) sh[tid] += sh[tid + off];
        __syncthreads();
    }
    if (tid == 0) s_boff = sh[0];
    __syncthreads();
    int boff = s_boff;
    __syncthreads();                      // sh about to be reused

    int i = blockIdx.x * SCAN_BS + tid;
    int v = (i < NUM_NODES) ? g_deg[i] : 0;
    sh[tid] = v;
    __syncthreads();
    for (int off = 1; off < SCAN_BS; off <<= 1) {
        int t = (tid >= off) ? sh[tid - off] : 0;
        __syncthreads();
        sh[tid] += t;
        __syncthreads();
    }
    if (i < NUM_NODES) {
        int excl = sh[tid] - v + boff;
        g_rowptr[i] = excl;
        g_cursor[i] = excl;
        if (i == NUM_NODES - 1) g_rowptr[NUM_NODES] = excl + v;
    }
}

// Fused: CSR scatter (src only) + layer-0 prescale (y0 = dinv*emb as fp16).
// Scalar, 1 edge / 1 half2 per thread (R11-proven form).
__global__ void k_scatter_prescale(const void* __restrict__ ei,
                                   const float* __restrict__ emb) {
    int e = blockIdx.x * blockDim.x + threadIdx.x;
    if (e < NUM_EDGES) {
        int s = load_idx(ei, 0, e);
        int d = load_idx(ei, 1, e);
        if (s >= 0 && d >= 0) {
            int pos = atomicAdd(&g_cursor[d], 1);
            if ((unsigned)pos < (unsigned)NUM_EDGES) g_csr_src[pos] = s;
        }
    }
    if (e < NUM_NODES * (EMBED_DIM / 2)) {
        int node = e >> 5;
        float sc = g_dinv[node];
        float2 v = ((const float2*)emb)[e];
        g_y0[e] = __floats2half2_rn(sc * v.x, sc * v.y);
    }
}

// SpMM, dual-edge scheme: one warp per dst row. Lanes 0-15 process even edges,
// lanes 16-31 odd edges; each lane loads a uint2 (2 half2 = 8B), so one
// LDG.64 + one SHFL serves TWO edges. In-batch accumulation in fp16 (HADD2,
// chain <= 16), flushed to fp32 per 32-edge batch. Even/odd partials merge via
// shfl_xor(16); epilogue is float4 by lanes 0-15.
//   acc[d] = Σ y[src]; x_next = dinv*acc; out += x_next/4; y_next = dinv*x_next
__global__ void k_spmm(const float* __restrict__ emb,
                       float* __restrict__ out,
                       int layer) {
    int row = blockIdx.x * (blockDim.x >> 5) + (threadIdx.x >> 5);
    if (row >= NUM_NODES) return;
    int lane = threadIdx.x & 31;
    int half_sel = lane >> 4;            // 0: even edges, 1: odd edges
    int col = lane & 15;                 // uint2 slot (covers cols 4*col..4*col+3)

    const uint2* yv = (const uint2*)((layer == 1) ? g_y1 : g_y0);
    __half2*     y_out = (layer == 0) ? g_y1 : g_y0;

    int beg = g_rowptr[row];
    int end = g_rowptr[row + 1];

    float4 accf = make_float4(0.f, 0.f, 0.f, 0.f);
    for (int b = beg; b < end; b += 32) {
        int n = end - b;
        __half2 a0 = __float2half2_rn(0.f);
        __half2 a1 = a0;
        if (n >= 32) {
            int s = g_csr_src[b + lane];
            #pragma unroll
            for (int k = 0; k < 16; ++k) {
                int sj = __shfl_sync(0xffffffffu, s, 2 * k + half_sel);
                uint2 hv = yv[(size_t)sj * 16 + col];
                a0 = __hadd2(a0, *(const __half2*)&hv.x);
                a1 = __hadd2(a1, *(const __half2*)&hv.y);
            }
        } else {
            int s = (lane < n) ? g_csr_src[b + lane] : -1;
            int pairs = (n + 1) >> 1;
            for (int k = 0; k < pairs; ++k) {
                int sj = __shfl_sync(0xffffffffu, s, 2 * k + half_sel);
                if (sj >= 0) {
                    uint2 hv = yv[(size_t)sj * 16 + col];
                    a0 = __hadd2(a0, *(const __half2*)&hv.x);
                    a1 = __hadd2(a1, *(const __half2*)&hv.y);
                }
            }
        }
        float2 f0 = __half22float2(a0);
        float2 f1 = __half22float2(a1);
        accf.x += f0.x; accf.y += f0.y;
        accf.z += f1.x; accf.w += f1.y;
    }

    // merge even-edge and odd-edge partial sums (partner lane = lane ^ 16)
    accf.x += __shfl_xor_sync(0xffffffffu, accf.x, 16);
    accf.y += __shfl_xor_sync(0xffffffffu, accf.y, 16);
    accf.z += __shfl_xor_sync(0xffffffffu, accf.z, 16);
    accf.w += __shfl_xor_sync(0xffffffffu, accf.w, 16);

    float di = g_dinv[row];
    float4 xn = make_float4(di * accf.x, di * accf.y, di * accf.z, di * accf.w);

    if (lane < 16) {
        if (layer != 2) {                // last layer's y is never read
            __half2 h0 = __floats2half2_rn(di * xn.x, di * xn.y);
            __half2 h1 = __floats2half2_rn(di * xn.z, di * xn.w);
            uint2 hv;
            hv.x = *(const unsigned*)&h0;
            hv.y = *(const unsigned*)&h1;
            ((uint2*)y_out)[(size_t)row * 16 + col] = hv;
        }
        float4* op = (float4*)(out + (size_t)row * EMBED_DIM) + col;
        const float inv = 1.0f / (NUM_LAYERS + 1);
        if (layer == 0) {
            float4 ev = ((const float4*)(emb + (size_t)row * EMBED_DIM))[col];
            *op = make_float4(inv * (ev.x + xn.x), inv * (ev.y + xn.y),
                              inv * (ev.z + xn.z), inv * (ev.w + xn.w));
        } else {
            float4 p = *op;
            *op = make_float4(p.x + inv * xn.x, p.y + inv * xn.y,
                              p.z + inv * xn.z, p.w + inv * xn.w);
        }
    }
}

// ---------------- launch ----------------

extern "C" void kernel_launch(void* const* d_in, const int* in_sizes, int n_in,
                              void* d_out, int out_size) {
    const float* emb = (const float*)d_in[0];
    const void*  ei  = d_in[1];          // int32 or int64 — detected on device
    float*       out = (float*)d_out;

    const int TB = 256;
    const int node_blocks = (NUM_NODES + TB - 1) / TB;
    const int edge_blocks = (NUM_EDGES + TB - 1) / TB;

    k_init<<<node_blocks, TB>>>(ei);
    k_hist<<<edge_blocks, TB>>>(ei);

    k_block_sums<<<SCAN_NB, SCAN_BS>>>();
    k_scan_blocks<<<SCAN_NB, SCAN_BS>>>();

    k_scatter_prescale<<<edge_blocks, TB>>>(ei, emb);

    const int WPB = TB / 32;                                   // 8 warps/block
    const int spmm_blocks = (NUM_NODES + WPB - 1) / WPB;       // 12500

    k_spmm<<<spmm_blocks, TB>>>(emb, out, 0);
    k_spmm<<<spmm_blocks, TB>>>(emb, out, 1);
    k_spmm<<<spmm_blocks, TB>>>(emb, out, 2);
}